// round 4
// baseline (speedup 1.0000x reference)
#include <cuda_runtime.h>
#include <cuda_bf16.h>
#include <cstdint>

// Shapes (fixed by dataset):
//   messages (B=32, E=8192, D=128) fp32 | tgt (B=32, E=8192) int32
//   out      (B=32, N=2048, D=128) fp32
static constexpr int B = 32;
static constexpr int E = 8192;
static constexpr int N = 2048;
static constexpr int D = 128;        // 32 float4 per row -> one warp handles a row
static constexpr int CAP = 16;       // bin capacity; Poisson(lambda=4) tail beyond 16 ~ 0
static constexpr int CELLS_PER_WARP = 2;
static constexpr int WARPS = 8;      // per block (gather)

// Scratch (device globals — allocations are forbidden).
// g_cnt[0 .. B*N-1] = per-cell edge counts; g_cnt[B*N] = overflow-list length.
__device__ int g_cnt [B * N + 1];          // 256 KB (+4)
__device__ int g_bins[B * N * CAP];        // 4 MiB : first CAP edge ids per cell
__device__ int g_over[2 * B * E];          // 2 MiB : (cell, edge) overflow pairs

// ── Phase 1: bin edges by (batch, target) ─────────────────────────────
__global__ __launch_bounds__(256) void bin_edges(const int* __restrict__ tgt) {
    const int e = blockIdx.x * 256 + threadIdx.x;      // global edge id
    const int t = __ldg(&tgt[e]);
    const int cell = ((e >> 13) * N) + t;              // b = e / 8192
    const int s = atomicAdd(&g_cnt[cell], 1);
    if (s < CAP) {
        g_bins[cell * CAP + s] = e;
    } else {                                           // vanishingly rare
        const int o = atomicAdd(&g_cnt[B * N], 1);
        g_over[2 * o]     = cell;
        g_over[2 * o + 1] = e;
    }
}

// ── Phase 2: gather — one warp per 2 output rows, zero atomics ────────
// Writes EVERY cell (zeros included) -> no output memset needed.
__global__ __launch_bounds__(WARPS * 32) void gather(
    const float4* __restrict__ messages,   // (B*E, 32) float4
    float4*       __restrict__ out)        // (B*N, 32) float4
{
    const int lane  = threadIdx.x & 31;
    const int warp  = blockIdx.x * WARPS + (threadIdx.x >> 5);
    const int cell0 = warp * CELLS_PER_WARP;
    const int cell1 = cell0 + 1;

    const int cnt0 = __ldg(&g_cnt[cell0]);
    const int cnt1 = __ldg(&g_cnt[cell1]);
    const int c0 = cnt0 < CAP ? cnt0 : CAP;
    const int c1 = cnt1 < CAP ? cnt1 : CAP;

    // Coalesced bin fetch: lane i holds edge id i of each cell.
    int e0 = 0, e1 = 0;
    if (lane < c0) e0 = __ldg(&g_bins[cell0 * CAP + lane]);
    if (lane < c1) e1 = __ldg(&g_bins[cell1 * CAP + lane]);

    float4 acc0 = make_float4(0.f, 0.f, 0.f, 0.f);
    float4 acc1 = make_float4(0.f, 0.f, 0.f, 0.f);

    const int cmax = c0 > c1 ? c0 : c1;
    for (int i = 0; i < cmax; i += 4) {
        float4 v0[4], v1[4];
#pragma unroll
        for (int j = 0; j < 4; j++) {               // up to 8 loads in flight
            v0[j] = make_float4(0.f, 0.f, 0.f, 0.f);
            v1[j] = make_float4(0.f, 0.f, 0.f, 0.f);
            if (i + j < c0) {
                const int r = __shfl_sync(0xFFFFFFFFu, e0, i + j);
                v0[j] = __ldcs(&messages[(size_t)r * 32 + lane]);
            }
            if (i + j < c1) {
                const int r = __shfl_sync(0xFFFFFFFFu, e1, i + j);
                v1[j] = __ldcs(&messages[(size_t)r * 32 + lane]);
            }
        }
#pragma unroll
        for (int j = 0; j < 4; j++) {
            acc0.x += v0[j].x; acc0.y += v0[j].y; acc0.z += v0[j].z; acc0.w += v0[j].w;
            acc1.x += v1[j].x; acc1.y += v1[j].y; acc1.z += v1[j].z; acc1.w += v1[j].w;
        }
    }

    // Overflow fold-in: normally n == 0 -> one broadcast scalar load, no loop.
    const int n = __ldg(&g_cnt[B * N]);
    for (int k = 0; k < n; k++) {
        const int oc = g_over[2 * k];
        if (oc == cell0 || oc == cell1) {
            const int r = g_over[2 * k + 1];
            const float4 v = __ldg(&messages[(size_t)r * 32 + lane]);
            if (oc == cell0) { acc0.x += v.x; acc0.y += v.y; acc0.z += v.z; acc0.w += v.w; }
            else             { acc1.x += v.x; acc1.y += v.y; acc1.z += v.z; acc1.w += v.w; }
        }
    }

    out[(size_t)cell0 * 32 + lane] = acc0;
    out[(size_t)cell1 * 32 + lane] = acc1;
}

extern "C" void kernel_launch(void* const* d_in, const int* in_sizes, int n_in,
                              void* d_out, int out_size)
{
    const float4* messages = (const float4*)d_in[0];
    const int*    tgt      = (const int*)d_in[1];

    // Zero counts + overflow length with one memset node (no kernel launch).
    void* cnt_ptr = nullptr;
    cudaGetSymbolAddress(&cnt_ptr, g_cnt);
    cudaMemsetAsync(cnt_ptr, 0, (size_t)(B * N + 1) * sizeof(int), 0);

    bin_edges<<<(B * E) / 256, 256>>>(tgt);

    const int cells_per_block = WARPS * CELLS_PER_WARP;         // 16
    gather<<<(B * N) / cells_per_block, WARPS * 32>>>(messages, (float4*)d_out);
}

// round 5
// speedup vs baseline: 1.1848x; 1.1848x over previous
#include <cuda_runtime.h>
#include <cuda_bf16.h>
#include <cstdint>

// Shapes (fixed by dataset):
//   messages (B=32, E=8192, D=128) fp32 | tgt (B=32, E=8192) int32
//   out      (B=32, N=2048, D=128) fp32
static constexpr int B = 32;
static constexpr int E = 8192;
static constexpr int N = 2048;
static constexpr int D = 128;               // 512 bytes per row
static constexpr int ROWS_PER_CHUNK = 32;   // 16 KB per smem buffer
static constexpr int THREADS = 256;
static constexpr int TOTAL_ROWS = B * E;                     // 262144
static constexpr int TOTAL_CHUNKS = TOTAL_ROWS / ROWS_PER_CHUNK;  // 8192
static constexpr int BLOCKS = 1024;
static constexpr int CHUNKS_PER_BLOCK = TOTAL_CHUNKS / BLOCKS;    // 8

// Sequential-stream scatter-add:
//  - messages are read as a fully-coalesced stream (LDG.128 -> STS), staged
//    in double-buffered smem chunks of 32 rows;
//  - each row is committed with ONE cp.reduce.async.bulk (512B f32 add,
//    element-atomic RMW at L2) instead of 32 RED.128 ops -> removes the
//    SM-side atomic-issue bottleneck diagnosed in R1/R2;
//  - output (32 MiB) stays L2-resident, so the RMW does not hit DRAM.
__global__ __launch_bounds__(THREADS) void scatter_bulk(
    const float4* __restrict__ messages,   // (TOTAL_ROWS, 32) float4
    const int*    __restrict__ tgt,        // (TOTAL_ROWS,)
    float*        __restrict__ out)        // (B*N*D,)
{
    __shared__ float4 buf[2][ROWS_PER_CHUNK * 32];   // 2 x 16 KB

    const int tid = threadIdx.x;
    const int chunk0 = blockIdx.x * CHUNKS_PER_BLOCK;

    // smem byte address of buf for async-proxy ops
    uint32_t smem_base;
    asm("{ .reg .u64 t; cvta.to.shared.u64 t, %1; cvt.u32.u64 %0, t; }"
        : "=r"(smem_base) : "l"(&buf[0][0]));

    for (int i = 0; i < CHUNKS_PER_BLOCK; i++) {
        const int p = i & 1;
        const int row0 = (chunk0 + i) * ROWS_PER_CHUNK;

        // Ensure the bulk-group issued 2 iterations ago (same buffer) has
        // finished READING smem before we overwrite it.
        if (tid < ROWS_PER_CHUNK)
            asm volatile("cp.async.bulk.wait_group.read 1;" ::: "memory");
        __syncthreads();

        // Stage 32 rows (16 KB) — fully coalesced stream, evict-first.
        const float4* src = messages + (size_t)row0 * 32;
#pragma unroll
        for (int k = 0; k < 4; k++)
            buf[p][k * THREADS + tid] = __ldcs(&src[k * THREADS + tid]);

        // One target index per row (coalesced 128B load by lanes 0..31).
        int cell = 0;
        if (tid < ROWS_PER_CHUNK) {
            const int e = row0 + tid;
            cell = ((e >> 13) * N) + __ldg(&tgt[e]);   // b = e / 8192
        }

        // Order generic-proxy smem writes before async-proxy bulk reads.
        asm volatile("fence.proxy.async.shared::cta;" ::: "memory");
        __syncthreads();

        // One bulk f32-add reduction per row: smem row -> out[cell].
        if (tid < ROWS_PER_CHUNK) {
            float* dst = out + (size_t)cell * D;
            uint32_t src_smem = smem_base
                              + (uint32_t)(p * ROWS_PER_CHUNK * 32 + tid * 32)
                                * (uint32_t)sizeof(float4);
            asm volatile(
                "cp.reduce.async.bulk.global.shared::cta.bulk_group.add.f32 "
                "[%0], [%1], %2;"
                :: "l"(dst), "r"(src_smem), "r"(D * 4)
                : "memory");
            asm volatile("cp.async.bulk.commit_group;" ::: "memory");
        }
    }

    // Do not release smem while bulk ops may still be reading it.
    if (tid < ROWS_PER_CHUNK)
        asm volatile("cp.async.bulk.wait_group.read 0;" ::: "memory");
}

extern "C" void kernel_launch(void* const* d_in, const int* in_sizes, int n_in,
                              void* d_out, int out_size)
{
    const float4* messages = (const float4*)d_in[0];
    const int*    tgt      = (const int*)d_in[1];

    // Output is poisoned before timing — zero it (graph-capturable memset node).
    cudaMemsetAsync(d_out, 0, (size_t)out_size * sizeof(float), 0);

    scatter_bulk<<<BLOCKS, THREADS>>>(messages, tgt, (float*)d_out);
}

// round 6
// speedup vs baseline: 1.3669x; 1.1537x over previous
#include <cuda_runtime.h>
#include <cuda_bf16.h>
#include <cstdint>

// Shapes (fixed by dataset):
//   messages (B=32, E=8192, D=128) fp32 | tgt (B=32, E=8192) int32
//   out      (B=32, N=2048, D=128) fp32
static constexpr int B = 32;
static constexpr int E = 8192;
static constexpr int N = 2048;
static constexpr int D = 128;                 // 512 B per row
static constexpr int TOTAL = B * E;           // 262144 rows

static constexpr int GRID    = 2048;
static constexpr int THREADS = 256;           // 8 warps
static constexpr int RED_WPB = 5;             // RED warps per block
static constexpr int TMA_WPB = 3;             // TMA warps per block
static constexpr int ROWS_PW = 16;            // rows per warp (both paths)
static constexpr int RED_TOTAL = GRID * RED_WPB * ROWS_PW;   // 163840 (62.5%)
static constexpr int DEPTH = 8;               // TMA slot ring per warp
// TMA rows: GRID * TMA_WPB * ROWS_PW = 98304 -> 163840 + 98304 = 262144 ✓

// Hybrid scatter-add: RED warps use the LSU atomic path (RED.128),
// TMA warps use cp.reduce.async.bulk (smem -> L2 RMW via the TMA engine).
// The two per-row cost walls (~34 cyc/warp-op LSU vs ~46 cyc/op TMA queue)
// sit on DIFFERENT units, so splitting the rows overlaps them.
__global__ __launch_bounds__(THREADS) void hybrid_scatter(
    const float4* __restrict__ messages,   // (TOTAL, 32) float4
    const int*    __restrict__ tgt,        // (TOTAL,)
    float*        __restrict__ out)        // (B*N*D,)
{
    __shared__ float4 slots[TMA_WPB][DEPTH][32];   // 12 KB

    const int wid  = threadIdx.x >> 5;
    const int lane = threadIdx.x & 31;

    if (wid < RED_WPB) {
        // ── RED path: 16 rows, 4-wide front-batched loads, RED.128 scatter ──
        const int warp = blockIdx.x * RED_WPB + wid;
        const int row0 = warp * ROWS_PW;

        int t = 0;
        if (lane < ROWS_PW) t = __ldg(&tgt[row0 + lane]);

#pragma unroll
        for (int i = 0; i < ROWS_PW; i += 4) {
            float4 v[4];
#pragma unroll
            for (int j = 0; j < 4; j++)
                v[j] = __ldcs(&messages[(size_t)(row0 + i + j) * 32 + lane]);
#pragma unroll
            for (int j = 0; j < 4; j++) {
                const int tr = __shfl_sync(0xFFFFFFFFu, t, i + j);
                const int b  = (row0 + i + j) >> 13;          // row / E
                float* dst = out + ((size_t)(b * N + tr) * D) + lane * 4;
                asm volatile(
                    "red.global.add.v4.f32 [%0], {%1, %2, %3, %4};"
                    :: "l"(dst), "f"(v[j].x), "f"(v[j].y), "f"(v[j].z), "f"(v[j].w)
                    : "memory");
            }
        }
    } else {
        // ── TMA path: stage each row in a private smem slot, one bulk f32-add
        //    reduce per row. Depth-8 ring, prefetched next-row load, no CTA sync.
        const int tw   = wid - RED_WPB;
        const int warp = blockIdx.x * TMA_WPB + tw;
        const int row0 = RED_TOTAL + warp * ROWS_PW;

        int t = 0;
        if (lane < ROWS_PW) t = __ldg(&tgt[row0 + lane]);

        float4 v = __ldcs(&messages[(size_t)row0 * 32 + lane]);

        for (int i = 0; i < ROWS_PW; i++) {
            // Prefetch next row while this one drains through the pipeline.
            float4 vn = make_float4(0.f, 0.f, 0.f, 0.f);
            if (i + 1 < ROWS_PW)
                vn = __ldcs(&messages[(size_t)(row0 + i + 1) * 32 + lane]);

            // Slot reuse guard: ≤ DEPTH-1 groups outstanding (lane 0 owns
            // the per-thread group counter; it is the only committer).
            if (lane == 0)
                asm volatile("cp.async.bulk.wait_group.read %0;"
                             :: "n"(DEPTH - 1) : "memory");
            __syncwarp();

            slots[tw][i & (DEPTH - 1)][lane] = v;
            asm volatile("fence.proxy.async.shared::cta;" ::: "memory");
            __syncwarp();

            // Warp-uniform target (shfl must be executed by all lanes).
            const int tr = __shfl_sync(0xFFFFFFFFu, t, i);
            const int b  = (row0 + i) >> 13;
            float* dst = out + (size_t)(b * N + tr) * D;

            if (lane == 0) {
                uint32_t src;
                asm("{ .reg .u64 u; cvta.to.shared.u64 u, %1; cvt.u32.u64 %0, u; }"
                    : "=r"(src) : "l"(&slots[tw][i & (DEPTH - 1)][0]));
                asm volatile(
                    "cp.reduce.async.bulk.global.shared::cta.bulk_group.add.f32 "
                    "[%0], [%1], %2;"
                    :: "l"(dst), "r"(src), "r"(D * 4) : "memory");
                asm volatile("cp.async.bulk.commit_group;" ::: "memory");
            }
            v = vn;
        }

        // Don't release smem while bulk ops may still be reading it.
        if (lane == 0)
            asm volatile("cp.async.bulk.wait_group.read 0;" ::: "memory");
        __syncwarp();
    }
}

extern "C" void kernel_launch(void* const* d_in, const int* in_sizes, int n_in,
                              void* d_out, int out_size)
{
    const float4* messages = (const float4*)d_in[0];
    const int*    tgt      = (const int*)d_in[1];

    // Output is poisoned before timing — zero it (graph-capturable memset node).
    cudaMemsetAsync(d_out, 0, (size_t)out_size * sizeof(float), 0);

    hybrid_scatter<<<GRID, THREADS>>>(messages, tgt, (float*)d_out);
}

// round 7
// speedup vs baseline: 1.5916x; 1.1644x over previous
#include <cuda_runtime.h>
#include <cuda_bf16.h>
#include <cstdint>

// Shapes (fixed by dataset):
//   messages (B=32, E=8192, D=128) fp32 | tgt (B=32, E=8192) int32
//   out      (B=32, N=2048, D=128) fp32
static constexpr int B = 32;
static constexpr int E = 8192;
static constexpr int N = 2048;
static constexpr int D = 128;                 // 512 B per row
static constexpr int TOTAL = B * E;           // 262144 rows

static constexpr int GRID    = 2048;
static constexpr int THREADS = 256;           // 8 warps
static constexpr int RED_WPB = 6;             // RED warps per block (75% of rows)
static constexpr int TMA_WPB = 2;             // TMA warps per block (25% of rows)
static constexpr int ROWS_PW = 16;
static constexpr int GRP     = 8;             // rows per TMA pipeline group
static constexpr int RED_TOTAL = GRID * RED_WPB * ROWS_PW;   // 196608
// TMA rows: GRID*TMA_WPB*ROWS_PW = 65536; 196608+65536 = 262144 ✓

__global__ __launch_bounds__(THREADS) void hybrid_scatter(
    const float4* __restrict__ messages,   // (TOTAL, 32) float4
    const int*    __restrict__ tgt,        // (TOTAL,)
    float*        __restrict__ out)        // (B*N*D,)
{
    // TMA staging: per TMA-warp, 2 buffers of 8 rows (4 KB each) -> 16 KB total
    __shared__ float4 buf[TMA_WPB][2][GRP][32];

    const int wid  = threadIdx.x >> 5;
    const int lane = threadIdx.x & 31;

    if (wid < RED_WPB) {
        // ── RED path: 16 rows/warp, 8-wide front-batched loads ──────────
        const int warp = blockIdx.x * RED_WPB + wid;
        const int row0 = warp * ROWS_PW;

        int t = 0;
        if (lane < ROWS_PW) t = __ldg(&tgt[row0 + lane]);

#pragma unroll
        for (int i = 0; i < ROWS_PW; i += 8) {
            float4 v[8];
#pragma unroll
            for (int j = 0; j < 8; j++)
                v[j] = __ldcs(&messages[(size_t)(row0 + i + j) * 32 + lane]);
#pragma unroll
            for (int j = 0; j < 8; j++) {
                const int tr = __shfl_sync(0xFFFFFFFFu, t, i + j);
                const int b  = (row0 + i + j) >> 13;          // row / E
                float* dst = out + ((size_t)(b * N + tr) * D) + lane * 4;
                asm volatile(
                    "red.global.add.v4.f32 [%0], {%1, %2, %3, %4};"
                    :: "l"(dst), "f"(v[j].x), "f"(v[j].y), "f"(v[j].z), "f"(v[j].w)
                    : "memory");
            }
        }
    } else {
        // ── TMA path: groups of 8 rows; fence/sync amortized over the group,
        //    one commit_group per 8 bulk-reduces, double-buffered smem ─────
        const int tw   = wid - RED_WPB;
        const int warp = blockIdx.x * TMA_WPB + tw;
        const int row0 = RED_TOTAL + warp * ROWS_PW;

        int t = 0;
        if (lane < ROWS_PW) t = __ldg(&tgt[row0 + lane]);

#pragma unroll
        for (int g = 0; g < ROWS_PW / GRP; g++) {
            const int p  = g & 1;
            const int rg = row0 + g * GRP;

            // Allow 1 group outstanding; wait before reusing this buffer.
            if (g >= 2 && lane == 0)
                asm volatile("cp.async.bulk.wait_group.read 1;" ::: "memory");
            __syncwarp();

            // 8 independent row loads in flight, then stage to smem.
            float4 v[GRP];
#pragma unroll
            for (int j = 0; j < GRP; j++)
                v[j] = __ldcs(&messages[(size_t)(rg + j) * 32 + lane]);
#pragma unroll
            for (int j = 0; j < GRP; j++)
                buf[tw][p][j][lane] = v[j];

            // One fence + one sync for the whole group.
            asm volatile("fence.proxy.async.shared::cta;" ::: "memory");
            __syncwarp();

            // Warp-uniform targets (shfl executed by all lanes).
            int cells[GRP];
#pragma unroll
            for (int j = 0; j < GRP; j++) {
                const int tr = __shfl_sync(0xFFFFFFFFu, t, g * GRP + j);
                cells[j] = (((rg + j) >> 13) * N) + tr;
            }

            if (lane == 0) {
#pragma unroll
                for (int j = 0; j < GRP; j++) {
                    uint32_t src;
                    asm("{ .reg .u64 u; cvta.to.shared.u64 u, %1; cvt.u32.u64 %0, u; }"
                        : "=r"(src) : "l"(&buf[tw][p][j][0]));
                    float* dst = out + (size_t)cells[j] * D;
                    asm volatile(
                        "cp.reduce.async.bulk.global.shared::cta.bulk_group.add.f32 "
                        "[%0], [%1], %2;"
                        :: "l"(dst), "r"(src), "r"(D * 4) : "memory");
                }
                asm volatile("cp.async.bulk.commit_group;" ::: "memory");
            }
        }

        // Don't release smem while bulk ops may still be reading it.
        if (lane == 0)
            asm volatile("cp.async.bulk.wait_group.read 0;" ::: "memory");
        __syncwarp();
    }
}

extern "C" void kernel_launch(void* const* d_in, const int* in_sizes, int n_in,
                              void* d_out, int out_size)
{
    const float4* messages = (const float4*)d_in[0];
    const int*    tgt      = (const int*)d_in[1];

    // Output is poisoned before timing — zero it (graph-capturable memset node).
    cudaMemsetAsync(d_out, 0, (size_t)out_size * sizeof(float), 0);

    hybrid_scatter<<<GRID, THREADS>>>(messages, tgt, (float*)d_out);
}